// round 3
// baseline (speedup 1.0000x reference)
#include <cuda_runtime.h>

typedef unsigned long long u64;

#define TT 32
#define BB 2048
#define DD 64
#define WWID 256
#define MROWS 16
#define NCTA (BB / MROWS)   // 128
#define NTHR 512

// Transposed weights, [k][n] layout so weight loads are lane-coalesced.
__device__ __align__(16) float g_W0t[DD * WWID];    // 64 x 256
__device__ __align__(16) float g_W1t[WWID * WWID];  // 256 x 256
__device__ __align__(16) float g_W2t[WWID * DD];    // 256 x 64

__global__ void prep_kernel(const float* __restrict__ W0,
                            const float* __restrict__ W1,
                            const float* __restrict__ W2) {
    int idx = blockIdx.x * blockDim.x + threadIdx.x;
    if (idx < DD * WWID) {              // W0t[k][n] = W0[n][k]
        int k = idx >> 8, n = idx & 255;
        g_W0t[idx] = W0[n * DD + k];
    }
    if (idx < WWID * WWID) {            // W1t[k][n] = W1[n][k]
        int k = idx >> 8, n = idx & 255;
        g_W1t[idx] = W1[n * WWID + k];
    }
    if (idx < WWID * DD) {              // W2t[k][d] = W2[d][k]
        int k = idx >> 6, d = idx & 63;
        g_W2t[idx] = W2[d * WWID + k];
    }
}

// ---- packed f32x2 helpers (ptxas never auto-fuses; must be PTX) ----
__device__ __forceinline__ u64 pk2(float x) {
    u64 r; asm("mov.b64 %0, {%1, %1};" : "=l"(r) : "f"(x)); return r;
}
__device__ __forceinline__ u64 fma2(u64 a, u64 b, u64 c) {
    u64 d; asm("fma.rn.f32x2 %0, %1, %2, %3;" : "=l"(d) : "l"(a), "l"(b), "l"(c));
    return d;
}
__device__ __forceinline__ void upk2(u64 v, float& lo, float& hi) {
    asm("mov.b64 {%0, %1}, %2;" : "=f"(lo), "=f"(hi) : "l"(v));
}

__device__ __forceinline__ float tanh_fast(float x) {
    // exact identity tanh(x) = 1 - 2/(e^{2x}+1); ~1e-6 abs err with fast exp/div
    float e = __expf(2.0f * x);
    return 1.0f - __fdividef(2.0f, e + 1.0f);
}

__device__ __forceinline__ float2 f2fma(float2 a, float s, float2 b) {
    a.x = fmaf(s, b.x, a.x); a.y = fmaf(s, b.y, a.y);
    return a;
}

// Hidden layer: out[16][256] = tanh(x[16][K] @ Wt(K x 256) + bias), 512 threads.
// Thread tile: 2 rows x 4 cols, math in packed f32x2.
// A-loads: warp-broadcast LDS.128. W-loads: coalesced LDG.128 (as ulonglong2).
__device__ __forceinline__ void dense_h(const float* __restrict__ x, int K,
                                        const float* __restrict__ Wt,
                                        const float* __restrict__ bias,
                                        float* __restrict__ o, int tid) {
    const int r0 = (tid >> 6) << 1;   // 0,2,...,14
    const int c0 = (tid & 63) << 2;   // 0..252
    u64 acc0a, acc0b, acc1a, acc1b;
    {
        ulonglong2 bv = *reinterpret_cast<const ulonglong2*>(bias + c0);
        acc0a = bv.x; acc0b = bv.y;
        acc1a = bv.x; acc1b = bv.y;
    }
    const float* xp0 = x + r0 * K;
    const float* xp1 = xp0 + K;
    const float* wp = Wt + c0;
    #pragma unroll 2
    for (int k = 0; k < K; k += 4) {
        float4 a0 = *reinterpret_cast<const float4*>(xp0 + k);
        float4 a1 = *reinterpret_cast<const float4*>(xp1 + k);
        ulonglong2 w0 = *reinterpret_cast<const ulonglong2*>(wp);
        ulonglong2 w1 = *reinterpret_cast<const ulonglong2*>(wp + 256);
        ulonglong2 w2 = *reinterpret_cast<const ulonglong2*>(wp + 512);
        ulonglong2 w3 = *reinterpret_cast<const ulonglong2*>(wp + 768);
        wp += 1024;
        u64 s;
        s = pk2(a0.x); acc0a = fma2(s, w0.x, acc0a); acc0b = fma2(s, w0.y, acc0b);
        s = pk2(a1.x); acc1a = fma2(s, w0.x, acc1a); acc1b = fma2(s, w0.y, acc1b);
        s = pk2(a0.y); acc0a = fma2(s, w1.x, acc0a); acc0b = fma2(s, w1.y, acc0b);
        s = pk2(a1.y); acc1a = fma2(s, w1.x, acc1a); acc1b = fma2(s, w1.y, acc1b);
        s = pk2(a0.z); acc0a = fma2(s, w2.x, acc0a); acc0b = fma2(s, w2.y, acc0b);
        s = pk2(a1.z); acc1a = fma2(s, w2.x, acc1a); acc1b = fma2(s, w2.y, acc1b);
        s = pk2(a0.w); acc0a = fma2(s, w3.x, acc0a); acc0b = fma2(s, w3.y, acc0b);
        s = pk2(a1.w); acc1a = fma2(s, w3.x, acc1a); acc1b = fma2(s, w3.y, acc1b);
    }
    float v0, v1, v2, v3;
    float4 r;
    upk2(acc0a, v0, v1); upk2(acc0b, v2, v3);
    r.x = tanh_fast(v0); r.y = tanh_fast(v1);
    r.z = tanh_fast(v2); r.w = tanh_fast(v3);
    *reinterpret_cast<float4*>(o + r0 * WWID + c0) = r;
    upk2(acc1a, v0, v1); upk2(acc1b, v2, v3);
    r.x = tanh_fast(v0); r.y = tanh_fast(v1);
    r.z = tanh_fast(v2); r.w = tanh_fast(v3);
    *reinterpret_cast<float4*>(o + (r0 + 1) * WWID + c0) = r;
}

// Output layer: k[16][64] = (x[16][256] @ W2t(256 x 64) + b2) * efac
// 512 threads: 1 row x 2 cols (one f32x2 accumulator per thread).
__device__ __forceinline__ void dense_o(const float* __restrict__ x,
                                        const float* __restrict__ Wt,
                                        const float* __restrict__ bias,
                                        float* __restrict__ o, float efac, int tid) {
    const int row = tid >> 5;         // 0..15
    const int c0 = (tid & 31) << 1;   // 0..62
    u64 acc = *reinterpret_cast<const u64*>(bias + c0);
    const float* xp = x + row * WWID;
    const float* wp = Wt + c0;
    #pragma unroll 4
    for (int k = 0; k < WWID; k += 4) {
        float4 a = *reinterpret_cast<const float4*>(xp + k);
        u64 w0 = *reinterpret_cast<const u64*>(wp);
        u64 w1 = *reinterpret_cast<const u64*>(wp + 64);
        u64 w2 = *reinterpret_cast<const u64*>(wp + 128);
        u64 w3 = *reinterpret_cast<const u64*>(wp + 192);
        wp += 256;
        acc = fma2(pk2(a.x), w0, acc);
        acc = fma2(pk2(a.y), w1, acc);
        acc = fma2(pk2(a.z), w2, acc);
        acc = fma2(pk2(a.w), w3, acc);
    }
    float lo, hi; upk2(acc, lo, hi);
    float2 r; r.x = lo * efac; r.y = hi * efac;
    *reinterpret_cast<float2*>(o + row * DD + c0) = r;
}

// smem layout (floats)
#define OFF_SY   0
#define OFF_SYT  (OFF_SY + MROWS * DD)        // 1024
#define OFF_SH0  (OFF_SYT + MROWS * DD)       // 2048
#define OFF_SH1  (OFF_SH0 + MROWS * WWID)     // 6144
#define OFF_SK   (OFF_SH1 + MROWS * WWID)     // 10240
#define OFF_SB0  (OFF_SK + 6 * MROWS * DD)    // 16384
#define OFF_SB1  (OFF_SB0 + WWID)             // 16640
#define OFF_SB2  (OFF_SB1 + WWID)             // 16896
#define OFF_STS  (OFF_SB2 + DD)               // 16960
#define SMEM_FLOATS (OFF_STS + TT)            // 16992

__global__ void __launch_bounds__(NTHR)
ode_kernel(const float* __restrict__ ts, const float* __restrict__ y0,
           const float* __restrict__ b0, const float* __restrict__ b1,
           const float* __restrict__ b2, float* __restrict__ out) {
    extern __shared__ float sm[];
    float* sy  = sm + OFF_SY;
    float* syt = sm + OFF_SYT;
    float* sh0 = sm + OFF_SH0;
    float* sh1 = sm + OFF_SH1;
    float* sk  = sm + OFF_SK;
    float* sb0 = sm + OFF_SB0;
    float* sb1 = sm + OFF_SB1;
    float* sb2 = sm + OFF_SB2;
    float* sts = sm + OFF_STS;

    const int tid = threadIdx.x;
    const int rb = blockIdx.x * MROWS;

    // Init: load y0 slice, biases, ts; write t=0 output slice.
    {
        float2 v = reinterpret_cast<const float2*>(y0)[rb * (DD / 2) + tid];
        reinterpret_cast<float2*>(sy)[tid] = v;
        reinterpret_cast<float2*>(out)[rb * (DD / 2) + tid] = v;
        if (tid < WWID) { sb0[tid] = b0[tid]; sb1[tid] = b1[tid]; }
        if (tid < DD) sb2[tid] = b2[tid];
        if (tid < TT) sts[tid] = ts[tid];
    }
    __syncthreads();

    float2* sy2  = reinterpret_cast<float2*>(sy);
    float2* syt2 = reinterpret_cast<float2*>(syt);
    float2* k12  = reinterpret_cast<float2*>(sk + 0 * MROWS * DD);
    float2* k22  = reinterpret_cast<float2*>(sk + 1 * MROWS * DD);
    float2* k32  = reinterpret_cast<float2*>(sk + 2 * MROWS * DD);
    float2* k42  = reinterpret_cast<float2*>(sk + 3 * MROWS * DD);
    float2* k52  = reinterpret_cast<float2*>(sk + 4 * MROWS * DD);
    float2* k62  = reinterpret_cast<float2*>(sk + 5 * MROWS * DD);

    for (int iv = 0; iv < TT - 1; ++iv) {
        const float t0 = sts[iv];
        const float dt = sts[iv + 1] - t0;
        const float h = 0.5f * dt;

        for (int sub = 0; sub < 2; ++sub) {
            const float tc = t0 + (float)sub * h;

            // ---- stage 1: k1 = vf(tc, y) ----
            dense_h(sy, DD, g_W0t, sb0, sh0, tid);  __syncthreads();
            dense_h(sh0, WWID, g_W1t, sb1, sh1, tid); __syncthreads();
            dense_o(sh1, g_W2t, sb2, sk + 0 * MROWS * DD, __expf(tc), tid); __syncthreads();

            // ---- stage 2 ----
            syt2[tid] = f2fma(sy2[tid], h * 0.2f, k12[tid]);
            __syncthreads();
            dense_h(syt, DD, g_W0t, sb0, sh0, tid);  __syncthreads();
            dense_h(sh0, WWID, g_W1t, sb1, sh1, tid); __syncthreads();
            dense_o(sh1, g_W2t, sb2, sk + 1 * MROWS * DD, __expf(tc + 0.2f * h), tid); __syncthreads();

            // ---- stage 3 ----
            {
                float2 v = sy2[tid];
                v = f2fma(v, h * (3.0f / 40.0f), k12[tid]);
                v = f2fma(v, h * (9.0f / 40.0f), k22[tid]);
                syt2[tid] = v;
            }
            __syncthreads();
            dense_h(syt, DD, g_W0t, sb0, sh0, tid);  __syncthreads();
            dense_h(sh0, WWID, g_W1t, sb1, sh1, tid); __syncthreads();
            dense_o(sh1, g_W2t, sb2, sk + 2 * MROWS * DD, __expf(tc + 0.3f * h), tid); __syncthreads();

            // ---- stage 4 ----
            {
                float2 v = sy2[tid];
                v = f2fma(v, h * (44.0f / 45.0f),  k12[tid]);
                v = f2fma(v, h * (-56.0f / 15.0f), k22[tid]);
                v = f2fma(v, h * (32.0f / 9.0f),   k32[tid]);
                syt2[tid] = v;
            }
            __syncthreads();
            dense_h(syt, DD, g_W0t, sb0, sh0, tid);  __syncthreads();
            dense_h(sh0, WWID, g_W1t, sb1, sh1, tid); __syncthreads();
            dense_o(sh1, g_W2t, sb2, sk + 3 * MROWS * DD, __expf(tc + 0.8f * h), tid); __syncthreads();

            // ---- stage 5 ----
            {
                float2 v = sy2[tid];
                v = f2fma(v, h * (19372.0f / 6561.0f),  k12[tid]);
                v = f2fma(v, h * (-25360.0f / 2187.0f), k22[tid]);
                v = f2fma(v, h * (64448.0f / 6561.0f),  k32[tid]);
                v = f2fma(v, h * (-212.0f / 729.0f),    k42[tid]);
                syt2[tid] = v;
            }
            __syncthreads();
            dense_h(syt, DD, g_W0t, sb0, sh0, tid);  __syncthreads();
            dense_h(sh0, WWID, g_W1t, sb1, sh1, tid); __syncthreads();
            dense_o(sh1, g_W2t, sb2, sk + 4 * MROWS * DD, __expf(tc + (8.0f / 9.0f) * h), tid); __syncthreads();

            // ---- stage 6 ----
            {
                float2 v = sy2[tid];
                v = f2fma(v, h * (9017.0f / 3168.0f),   k12[tid]);
                v = f2fma(v, h * (-355.0f / 33.0f),     k22[tid]);
                v = f2fma(v, h * (46732.0f / 5247.0f),  k32[tid]);
                v = f2fma(v, h * (49.0f / 176.0f),      k42[tid]);
                v = f2fma(v, h * (-5103.0f / 18656.0f), k52[tid]);
                syt2[tid] = v;
            }
            __syncthreads();
            dense_h(syt, DD, g_W0t, sb0, sh0, tid);  __syncthreads();
            dense_h(sh0, WWID, g_W1t, sb1, sh1, tid); __syncthreads();
            dense_o(sh1, g_W2t, sb2, sk + 5 * MROWS * DD, __expf(tc + h), tid); __syncthreads();

            // ---- final combine ----
            {
                float2 v = sy2[tid];
                v = f2fma(v, h * (35.0f / 384.0f),     k12[tid]);
                v = f2fma(v, h * (500.0f / 1113.0f),   k32[tid]);
                v = f2fma(v, h * (125.0f / 192.0f),    k42[tid]);
                v = f2fma(v, h * (-2187.0f / 6784.0f), k52[tid]);
                v = f2fma(v, h * (11.0f / 84.0f),      k62[tid]);
                sy2[tid] = v;
            }
            __syncthreads();
        }

        // write output slice (iv+1)
        reinterpret_cast<float2*>(out)[((iv + 1) * BB + rb) * (DD / 2) + tid] = sy2[tid];
    }
}

extern "C" void kernel_launch(void* const* d_in, const int* in_sizes, int n_in,
                              void* d_out, int out_size) {
    const float* ts = (const float*)d_in[0];
    const float* y0 = (const float*)d_in[1];
    const float* W0 = (const float*)d_in[2];
    const float* b0 = (const float*)d_in[3];
    const float* W1 = (const float*)d_in[4];
    const float* b1 = (const float*)d_in[5];
    const float* W2 = (const float*)d_in[6];
    const float* b2 = (const float*)d_in[7];
    float* out = (float*)d_out;

    prep_kernel<<<256, 256>>>(W0, W1, W2);

    size_t smem_bytes = SMEM_FLOATS * sizeof(float);
    cudaFuncSetAttribute(ode_kernel, cudaFuncAttributeMaxDynamicSharedMemorySize,
                         (int)smem_bytes);
    ode_kernel<<<NCTA, NTHR, smem_bytes>>>(ts, y0, b0, b1, b2, out);
}